// round 6
// baseline (speedup 1.0000x reference)
#include <cuda_runtime.h>
#include <cuda_fp16.h>

#define NNODES 50000
#define DIM    128
#define NHOPS  3
#define SIGMA_F 0.1f
#define MAXE   800000
#define NCHUNK 196            // ceil(50000/256)

// ---------------------------------------------------------------------------
// Scratch (__device__ globals — allocation-free rule)
// ---------------------------------------------------------------------------
__device__ int  g_cnt[NNODES];        // in-degree histogram
__device__ int  g_off[NNODES + 1];    // segment offsets (CSR by dst)
__device__ int  g_cur[NNODES];        // scatter cursors
__device__ int  g_src[MAXE];          // src indices sorted by dst
__device__ int  g_part[256];          // block partial sums for scan
__device__ __align__(16) half g_h16[2][NNODES * DIM];  // fp16 ping-pong h

// ---------------------------------------------------------------------------
// Threefry-2x32 (20 rounds) — matches JAX bit-for-bit (verified R2)
// ---------------------------------------------------------------------------
__host__ __device__ __forceinline__ void tf_round(unsigned& x0, unsigned& x1, int r) {
    x0 += x1;
#ifdef __CUDA_ARCH__
    x1 = __funnelshift_l(x1, x1, r);
#else
    x1 = (x1 << r) | (x1 >> (32 - r));
#endif
    x1 ^= x0;
}

__host__ __device__ __forceinline__ void threefry2x32(
    unsigned k0, unsigned k1, unsigned x0, unsigned x1,
    unsigned& o0, unsigned& o1)
{
    unsigned k2 = k0 ^ k1 ^ 0x1BD11BDAu;
    x0 += k0; x1 += k1;
    tf_round(x0,x1,13); tf_round(x0,x1,15); tf_round(x0,x1,26); tf_round(x0,x1, 6);
    x0 += k1; x1 += k2 + 1u;
    tf_round(x0,x1,17); tf_round(x0,x1,29); tf_round(x0,x1,16); tf_round(x0,x1,24);
    x0 += k2; x1 += k0 + 2u;
    tf_round(x0,x1,13); tf_round(x0,x1,15); tf_round(x0,x1,26); tf_round(x0,x1, 6);
    x0 += k0; x1 += k1 + 3u;
    tf_round(x0,x1,17); tf_round(x0,x1,29); tf_round(x0,x1,16); tf_round(x0,x1,24);
    x0 += k1; x1 += k2 + 4u;
    tf_round(x0,x1,13); tf_round(x0,x1,15); tf_round(x0,x1,26); tf_round(x0,x1, 6);
    x0 += k2; x1 += k0 + 5u;
    o0 = x0; o1 = x1;
}

// XLA ErfInv32 polynomial (Giles)
__device__ __forceinline__ float erfinv_f(float x) {
    float w = -log1pf(-x * x);
    float p;
    if (w < 5.0f) {
        w -= 2.5f;
        p =              2.81022636e-08f;
        p = fmaf(p, w,   3.43273939e-07f);
        p = fmaf(p, w,  -3.5233877e-06f);
        p = fmaf(p, w,  -4.39150654e-06f);
        p = fmaf(p, w,   0.00021858087f);
        p = fmaf(p, w,  -0.00125372503f);
        p = fmaf(p, w,  -0.00417768164f);
        p = fmaf(p, w,   0.246640727f);
        p = fmaf(p, w,   1.50140941f);
    } else {
        w = sqrtf(w) - 3.0f;
        p =             -0.000200214257f;
        p = fmaf(p, w,   0.000100950558f);
        p = fmaf(p, w,   0.00134934322f);
        p = fmaf(p, w,  -0.00367342844f);
        p = fmaf(p, w,   0.00573950773f);
        p = fmaf(p, w,  -0.0076224613f);
        p = fmaf(p, w,   0.00943887047f);
        p = fmaf(p, w,   1.00167406f);
        p = fmaf(p, w,   2.83297682f);
    }
    return p * x;
}

__device__ __forceinline__ float jax_normal(unsigned k0, unsigned k1, unsigned idx) {
    unsigned o0, o1;
    threefry2x32(k0, k1, 0u, idx, o0, o1);
    unsigned bits = o0 ^ o1;
    float u01 = __uint_as_float((bits >> 9) | 0x3F800000u) - 1.0f;
    const float LO = -0.99999994f;          // nextafterf(-1, 0)
    float u = fmaxf(LO, u01 * 2.0f + LO);   // (1.0f - LO) rounds to exactly 2.0f
    return 1.41421356f * erfinv_f(u);       // sqrt(2) in f32
}

// ---------------------------------------------------------------------------
// edge-index dtype detection, inlined (int64 values < 50000 -> odd words zero)
// ---------------------------------------------------------------------------
__device__ __forceinline__ int detect64(const void* ei) {
    const unsigned* w = (const unsigned*)ei;
    return ((w[1] == 0u) + (w[3] == 0u) + (w[5] == 0u) + (w[7] == 0u) + (w[9] == 0u)) == 5;
}

__device__ __forceinline__ void load_edge(const void* ei, int is64, int e, int E,
                                          int& s, int& d) {
    if (is64) {
        const long long* p = (const long long*)ei;
        s = (int)__ldg(p + e);
        d = (int)__ldg(p + e + E);
    } else {
        const int* p = (const int*)ei;
        s = __ldg(p + e);
        d = __ldg(p + e + E);
    }
}

// ---------------------------------------------------------------------------
// fp16 row helpers: 4 dims per lane (8 bytes)
// ---------------------------------------------------------------------------
__device__ __forceinline__ float4 ld_h16(const half* __restrict__ base, int row, int lane) {
    uint2 u = __ldg((const uint2*)(base + (size_t)row * DIM) + lane);
    half2 h0 = *(half2*)&u.x, h1 = *(half2*)&u.y;
    float2 f0 = __half22float2(h0), f1 = __half22float2(h1);
    return make_float4(f0.x, f0.y, f1.x, f1.y);
}

__device__ __forceinline__ void st_h16(half* __restrict__ base, int row, int lane, float4 v) {
    half2 h0 = __floats2half2_rn(v.x, v.y);
    half2 h1 = __floats2half2_rn(v.z, v.w);
    uint2 u;
    u.x = *(unsigned*)&h0;
    u.y = *(unsigned*)&h1;
    *((uint2*)(base + (size_t)row * DIM) + lane) = u;
}

// ---------------------------------------------------------------------------
// init: h0 = normalize(x) -> out[0] (fp32) + g_h16[0]; zero histogram.
// ---------------------------------------------------------------------------
__global__ __launch_bounds__(256) void init_kernel(
    const float* __restrict__ x, float* __restrict__ out0)
{
    int gt = blockIdx.x * blockDim.x + threadIdx.x;
    if (gt < NNODES) g_cnt[gt] = 0;
    int row  = gt >> 5;
    int lane = threadIdx.x & 31;
    if (row >= NNODES) return;
    float4 v = __ldg((const float4*)(x + (size_t)row * DIM) + lane);
    float ss = v.x*v.x + v.y*v.y + v.z*v.z + v.w*v.w;
#pragma unroll
    for (int o = 16; o; o >>= 1) ss += __shfl_xor_sync(0xffffffffu, ss, o);
    float inv = 1.0f / fmaxf(sqrtf(ss), 1e-12f);
    v.x *= inv; v.y *= inv; v.z *= inv; v.w *= inv;
    ((float4*)(out0 + (size_t)row * DIM))[lane] = v;
    st_h16(g_h16[0], row, lane, v);
}

// ---------------------------------------------------------------------------
// counting sort by dst: histogram -> 3-pass scan -> scatter
// ---------------------------------------------------------------------------
__global__ __launch_bounds__(256) void hist_kernel(const void* __restrict__ ei, int E) {
    int is64 = detect64(ei);
    for (int e = blockIdx.x * blockDim.x + threadIdx.x; e < E; e += gridDim.x * blockDim.x) {
        int s, d; load_edge(ei, is64, e, E, s, d);
        atomicAdd(&g_cnt[d], 1);
    }
}

__global__ __launch_bounds__(256) void scan1_kernel() {
    __shared__ int sm[8];
    int t = threadIdx.x;
    int i = blockIdx.x * 256 + t;
    int v = (i < NNODES) ? g_cnt[i] : 0;
#pragma unroll
    for (int o = 16; o; o >>= 1) v += __shfl_xor_sync(0xffffffffu, v, o);
    if ((t & 31) == 0) sm[t >> 5] = v;
    __syncthreads();
    if (t == 0) {
        int s = 0;
#pragma unroll
        for (int w = 0; w < 8; ++w) s += sm[w];
        g_part[blockIdx.x] = s;
    }
}

__global__ __launch_bounds__(256) void scan2_kernel() {
    __shared__ int sm[256];
    int t = threadIdx.x;
    sm[t] = (t < NCHUNK) ? g_part[t] : 0;
    __syncthreads();
#pragma unroll
    for (int o = 1; o < 256; o <<= 1) {
        int add = (t >= o) ? sm[t - o] : 0;
        __syncthreads();
        sm[t] += add;
        __syncthreads();
    }
    if (t < NCHUNK) g_part[t] = (t == 0) ? 0 : sm[t - 1];   // exclusive
}

__global__ __launch_bounds__(256) void scan3_kernel(int E) {
    __shared__ int sm[256];
    int t = threadIdx.x;
    int i = blockIdx.x * 256 + t;
    int v = (i < NNODES) ? g_cnt[i] : 0;
    sm[t] = v;
    __syncthreads();
#pragma unroll
    for (int o = 1; o < 256; o <<= 1) {
        int add = (t >= o) ? sm[t - o] : 0;
        __syncthreads();
        sm[t] += add;
        __syncthreads();
    }
    int excl = (t == 0) ? 0 : sm[t - 1];
    int off = g_part[blockIdx.x] + excl;
    if (i < NNODES) { g_off[i] = off; g_cur[i] = off; }
    if (blockIdx.x == 0 && t == 0) g_off[NNODES] = E;
}

__global__ __launch_bounds__(256) void scatter_kernel(const void* __restrict__ ei, int E) {
    int is64 = detect64(ei);
    for (int e = blockIdx.x * blockDim.x + threadIdx.x; e < E; e += gridDim.x * blockDim.x) {
        int s, d; load_edge(ei, is64, e, E, s, d);
        int pos = atomicAdd(&g_cur[d], 1);
        g_src[pos] = s;
    }
}

// ---------------------------------------------------------------------------
// fused hop: one warp per dst node. fp16 gathers, fp32 math.
// 2-edge software pipeline: two independent butterfly chains per iteration.
// ---------------------------------------------------------------------------
__global__ __launch_bounds__(256) void hop_fused_kernel(
    float* __restrict__ out, int bank, unsigned k0, unsigned k1)
{
    int row  = (blockIdx.x * blockDim.x + threadIdx.x) >> 5;
    int lane = threadIdx.x & 31;
    if (row >= NNODES) return;

    const half* __restrict__ hin  = g_h16[bank];
    half*       __restrict__ hout = g_h16[bank ^ 1];

    int start = g_off[row];
    int end   = g_off[row + 1];

    float4 b = ld_h16(hin, row, lane);
    float4 acc = make_float4(0.f, 0.f, 0.f, 0.f);

    for (int j0 = start; j0 < end; j0 += 32) {
        int n = min(32, end - j0);
        int idx = (lane < n) ? __ldg(g_src + j0 + lane) : 0;

        // 2-deep software pipeline on the gather, 2 parallel dot chains
        float4 a0, a1;
        {
            int s0 = __shfl_sync(0xffffffffu, idx, 0);
            a0 = ld_h16(hin, s0, lane);
        }
        if (n > 1) {
            int s1 = __shfl_sync(0xffffffffu, idx, 1);
            a1 = ld_h16(hin, s1, lane);
        }

        for (int t = 0; t < n; t += 2) {
            float4 c0 = a0, c1 = a1;
            bool have1 = (t + 1 < n);
            if (t + 2 < n) {
                int sn = __shfl_sync(0xffffffffu, idx, t + 2);
                a0 = ld_h16(hin, sn, lane);
            }
            if (t + 3 < n) {
                int sn = __shfl_sync(0xffffffffu, idx, t + 3);
                a1 = ld_h16(hin, sn, lane);
            }

            float d0 = c0.x*b.x + c0.y*b.y + c0.z*b.z + c0.w*b.w;
            float d1 = c1.x*b.x + c1.y*b.y + c1.z*b.z + c1.w*b.w;
#pragma unroll
            for (int o = 16; o; o >>= 1) {
                d0 += __shfl_xor_sync(0xffffffffu, d0, o);
                d1 += __shfl_xor_sync(0xffffffffu, d1, o);
            }
            float alpha0 = __fdividef(1.0f, 1.0f + __expf(-d0));
            acc.x = fmaf(alpha0, c0.x, acc.x);
            acc.y = fmaf(alpha0, c0.y, acc.y);
            acc.z = fmaf(alpha0, c0.z, acc.z);
            acc.w = fmaf(alpha0, c0.w, acc.w);
            if (have1) {
                float alpha1 = __fdividef(1.0f, 1.0f + __expf(-d1));
                acc.x = fmaf(alpha1, c1.x, acc.x);
                acc.y = fmaf(alpha1, c1.y, acc.y);
                acc.z = fmaf(alpha1, c1.z, acc.z);
                acc.w = fmaf(alpha1, c1.w, acc.w);
            }
        }
    }

    unsigned base = (unsigned)row * DIM + (unsigned)lane * 4;
    acc.x += SIGMA_F * jax_normal(k0, k1, base + 0);
    acc.y += SIGMA_F * jax_normal(k0, k1, base + 1);
    acc.z += SIGMA_F * jax_normal(k0, k1, base + 2);
    acc.w += SIGMA_F * jax_normal(k0, k1, base + 3);

    float ss = acc.x*acc.x + acc.y*acc.y + acc.z*acc.z + acc.w*acc.w;
#pragma unroll
    for (int o = 16; o; o >>= 1) ss += __shfl_xor_sync(0xffffffffu, ss, o);
    float inv = 1.0f / fmaxf(sqrtf(ss), 1e-12f);
    acc.x *= inv; acc.y *= inv; acc.z *= inv; acc.w *= inv;

    ((float4*)(out + (size_t)row * DIM))[lane] = acc;
    st_h16(hout, row, lane, acc);
}

// ---------------------------------------------------------------------------
// launch
// ---------------------------------------------------------------------------
extern "C" void kernel_launch(void* const* d_in, const int* in_sizes, int n_in,
                              void* d_out, int out_size)
{
    int i_x = 0, i_e = 1;
    if (in_sizes[0] != NNODES * DIM) { i_x = 1; i_e = 0; }
    const float* x  = (const float*)d_in[i_x];
    const void*  ei = d_in[i_e];
    int E = in_sizes[i_e] / 2;

    float* out = (float*)d_out;

    // fold-like split of jax.random.key(1) into NHOPS subkeys (exact)
    unsigned keys[NHOPS][2];
    for (unsigned k = 0; k < NHOPS; ++k)
        threefry2x32(0u, 1u, 0u, k, keys[k][0], keys[k][1]);

    const int ROW_BLOCKS  = (NNODES * 32 + 255) / 256;
    const int EDGE_BLOCKS = (E + 255) / 256;

    init_kernel<<<ROW_BLOCKS, 256>>>(x, out);
    hist_kernel<<<EDGE_BLOCKS, 256>>>(ei, E);
    scan1_kernel<<<NCHUNK, 256>>>();
    scan2_kernel<<<1, 256>>>();
    scan3_kernel<<<NCHUNK, 256>>>(E);
    scatter_kernel<<<EDGE_BLOCKS, 256>>>(ei, E);

    for (int k = 0; k < NHOPS; ++k) {
        hop_fused_kernel<<<ROW_BLOCKS, 256>>>(out + (size_t)(k + 1) * NNODES * DIM,
                                              k & 1, keys[k][0], keys[k][1]);
    }
}

// round 8
// speedup vs baseline: 1.1159x; 1.1159x over previous
#include <cuda_runtime.h>

#define NNODES 50000
#define DIM    128
#define NHOPS  3
#define SIGMA_F 0.1f
#define MAXE   800000
#define NCHUNK 196            // ceil(50000/256)

// ---------------------------------------------------------------------------
// Scratch (__device__ globals — allocation-free rule).
// g_cnt invariant: zeroed at end of every kernel_launch (scan3), and statics
// are zero-initialized at load, so hist_kernel never needs a zeroing pass.
// ---------------------------------------------------------------------------
__device__ int g_cnt[NNODES];        // in-degree histogram
__device__ int g_off[NNODES + 1];    // segment offsets (CSR by dst)
__device__ int g_cur[NNODES];        // scatter cursors
__device__ int g_src[MAXE];          // src indices sorted by dst
__device__ int g_part[256];          // block partial sums for scan

// ---------------------------------------------------------------------------
// Threefry-2x32 (20 rounds) — matches JAX bit-for-bit (verified R2)
// ---------------------------------------------------------------------------
__host__ __device__ __forceinline__ void tf_round(unsigned& x0, unsigned& x1, int r) {
    x0 += x1;
#ifdef __CUDA_ARCH__
    x1 = __funnelshift_l(x1, x1, r);
#else
    x1 = (x1 << r) | (x1 >> (32 - r));
#endif
    x1 ^= x0;
}

__host__ __device__ __forceinline__ void threefry2x32(
    unsigned k0, unsigned k1, unsigned x0, unsigned x1,
    unsigned& o0, unsigned& o1)
{
    unsigned k2 = k0 ^ k1 ^ 0x1BD11BDAu;
    x0 += k0; x1 += k1;
    tf_round(x0,x1,13); tf_round(x0,x1,15); tf_round(x0,x1,26); tf_round(x0,x1, 6);
    x0 += k1; x1 += k2 + 1u;
    tf_round(x0,x1,17); tf_round(x0,x1,29); tf_round(x0,x1,16); tf_round(x0,x1,24);
    x0 += k2; x1 += k0 + 2u;
    tf_round(x0,x1,13); tf_round(x0,x1,15); tf_round(x0,x1,26); tf_round(x0,x1, 6);
    x0 += k0; x1 += k1 + 3u;
    tf_round(x0,x1,17); tf_round(x0,x1,29); tf_round(x0,x1,16); tf_round(x0,x1,24);
    x0 += k1; x1 += k2 + 4u;
    tf_round(x0,x1,13); tf_round(x0,x1,15); tf_round(x0,x1,26); tf_round(x0,x1, 6);
    x0 += k2; x1 += k0 + 5u;
    o0 = x0; o1 = x1;
}

// XLA ErfInv32 polynomial (Giles)
__device__ __forceinline__ float erfinv_f(float x) {
    float w = -log1pf(-x * x);
    float p;
    if (w < 5.0f) {
        w -= 2.5f;
        p =              2.81022636e-08f;
        p = fmaf(p, w,   3.43273939e-07f);
        p = fmaf(p, w,  -3.5233877e-06f);
        p = fmaf(p, w,  -4.39150654e-06f);
        p = fmaf(p, w,   0.00021858087f);
        p = fmaf(p, w,  -0.00125372503f);
        p = fmaf(p, w,  -0.00417768164f);
        p = fmaf(p, w,   0.246640727f);
        p = fmaf(p, w,   1.50140941f);
    } else {
        w = sqrtf(w) - 3.0f;
        p =             -0.000200214257f;
        p = fmaf(p, w,   0.000100950558f);
        p = fmaf(p, w,   0.00134934322f);
        p = fmaf(p, w,  -0.00367342844f);
        p = fmaf(p, w,   0.00573950773f);
        p = fmaf(p, w,  -0.0076224613f);
        p = fmaf(p, w,   0.00943887047f);
        p = fmaf(p, w,   1.00167406f);
        p = fmaf(p, w,   2.83297682f);
    }
    return p * x;
}

__device__ __forceinline__ float jax_normal(unsigned k0, unsigned k1, unsigned idx) {
    unsigned o0, o1;
    threefry2x32(k0, k1, 0u, idx, o0, o1);
    unsigned bits = o0 ^ o1;
    float u01 = __uint_as_float((bits >> 9) | 0x3F800000u) - 1.0f;
    const float LO = -0.99999994f;          // nextafterf(-1, 0)
    float u = fmaxf(LO, u01 * 2.0f + LO);   // (1.0f - LO) rounds to exactly 2.0f
    return 1.41421356f * erfinv_f(u);       // sqrt(2) in f32
}

// ---------------------------------------------------------------------------
// edge-index dtype detection, inlined (int64 values < 50000 -> odd words zero)
// ---------------------------------------------------------------------------
__device__ __forceinline__ int detect64(const void* ei) {
    const unsigned* w = (const unsigned*)ei;
    return ((w[1] == 0u) + (w[3] == 0u) + (w[5] == 0u) + (w[7] == 0u) + (w[9] == 0u)) == 5;
}

__device__ __forceinline__ void load_edge(const void* ei, int is64, int e, int E,
                                          int& s, int& d) {
    if (is64) {
        const long long* p = (const long long*)ei;
        s = (int)__ldg(p + e);
        d = (int)__ldg(p + e + E);
    } else {
        const int* p = (const int*)ei;
        s = __ldg(p + e);
        d = __ldg(p + e + E);
    }
}

__device__ __forceinline__ float4 ld_row(const float* __restrict__ h, int row, int lane) {
    return __ldg((const float4*)(h + (size_t)row * DIM) + lane);
}

// ---------------------------------------------------------------------------
// init: h0 = normalize(x) -> out[0]. One warp per row.
// ---------------------------------------------------------------------------
__global__ __launch_bounds__(256) void init_kernel(
    const float* __restrict__ x, float* __restrict__ out0)
{
    int gt   = blockIdx.x * blockDim.x + threadIdx.x;
    int row  = gt >> 5;
    int lane = threadIdx.x & 31;
    if (row >= NNODES) return;
    float4 v = __ldg((const float4*)(x + (size_t)row * DIM) + lane);
    float ss = v.x*v.x + v.y*v.y + v.z*v.z + v.w*v.w;
#pragma unroll
    for (int o = 16; o; o >>= 1) ss += __shfl_xor_sync(0xffffffffu, ss, o);
    float inv = 1.0f / fmaxf(sqrtf(ss), 1e-12f);
    v.x *= inv; v.y *= inv; v.z *= inv; v.w *= inv;
    ((float4*)(out0 + (size_t)row * DIM))[lane] = v;
}

// ---------------------------------------------------------------------------
// counting sort by dst: histogram -> 3-pass scan -> scatter
// ---------------------------------------------------------------------------
__global__ __launch_bounds__(256) void hist_kernel(const void* __restrict__ ei, int E) {
    int is64 = detect64(ei);
    for (int e = blockIdx.x * blockDim.x + threadIdx.x; e < E; e += gridDim.x * blockDim.x) {
        int s, d; load_edge(ei, is64, e, E, s, d);
        atomicAdd(&g_cnt[d], 1);
    }
}

__global__ __launch_bounds__(256) void scan1_kernel() {
    __shared__ int sm[8];
    int t = threadIdx.x;
    int i = blockIdx.x * 256 + t;
    int v = (i < NNODES) ? g_cnt[i] : 0;
#pragma unroll
    for (int o = 16; o; o >>= 1) v += __shfl_xor_sync(0xffffffffu, v, o);
    if ((t & 31) == 0) sm[t >> 5] = v;
    __syncthreads();
    if (t == 0) {
        int s = 0;
#pragma unroll
        for (int w = 0; w < 8; ++w) s += sm[w];
        g_part[blockIdx.x] = s;
    }
}

__global__ __launch_bounds__(256) void scan2_kernel() {
    __shared__ int sm[256];
    int t = threadIdx.x;
    sm[t] = (t < NCHUNK) ? g_part[t] : 0;
    __syncthreads();
#pragma unroll
    for (int o = 1; o < 256; o <<= 1) {
        int add = (t >= o) ? sm[t - o] : 0;
        __syncthreads();
        sm[t] += add;
        __syncthreads();
    }
    if (t < NCHUNK) g_part[t] = (t == 0) ? 0 : sm[t - 1];   // exclusive
}

__global__ __launch_bounds__(256) void scan3_kernel(int E) {
    __shared__ int sm[256];
    int t = threadIdx.x;
    int i = blockIdx.x * 256 + t;
    int v = (i < NNODES) ? g_cnt[i] : 0;
    if (i < NNODES) g_cnt[i] = 0;      // restore zeroed invariant for next call
    sm[t] = v;
    __syncthreads();
#pragma unroll
    for (int o = 1; o < 256; o <<= 1) {
        int add = (t >= o) ? sm[t - o] : 0;
        __syncthreads();
        sm[t] += add;
        __syncthreads();
    }
    int excl = (t == 0) ? 0 : sm[t - 1];
    int off = g_part[blockIdx.x] + excl;
    if (i < NNODES) { g_off[i] = off; g_cur[i] = off; }
    if (blockIdx.x == 0 && t == 0) g_off[NNODES] = E;
}

__global__ __launch_bounds__(256) void scatter_kernel(const void* __restrict__ ei, int E) {
    int is64 = detect64(ei);
    for (int e = blockIdx.x * blockDim.x + threadIdx.x; e < E; e += gridDim.x * blockDim.x) {
        int s, d; load_edge(ei, is64, e, E, s, d);
        int pos = atomicAdd(&g_cur[d], 1);
        g_src[pos] = s;
    }
}

// ---------------------------------------------------------------------------
// fused hop: one warp per dst node. 4-edge-wide interleaved butterflies +
// 1-group-deep gather prefetch. Branch-free tail via clamped lanes + SEL.
// ---------------------------------------------------------------------------
__global__ __launch_bounds__(256) void hop_fused_kernel(
    const float* __restrict__ h, float* __restrict__ out,
    unsigned k0, unsigned k1)
{
    int row  = (blockIdx.x * blockDim.x + threadIdx.x) >> 5;
    int lane = threadIdx.x & 31;
    if (row >= NNODES) return;

    int start = g_off[row];
    int end   = g_off[row + 1];

    float4 b = ld_row(h, row, lane);
    float4 acc = make_float4(0.f, 0.f, 0.f, 0.f);

    for (int j0 = start; j0 < end; j0 += 32) {
        int n = min(32, end - j0);                       // n >= 1
        int idx = __ldg(g_src + j0 + min(lane, n - 1));  // clamped, always valid

        // prefetch group 0 (clamped broadcast lanes; duplicates are L1 hits)
        float4 a0, a1, a2, a3;
        {
            int s0 = __shfl_sync(0xffffffffu, idx, 0);
            int s1 = __shfl_sync(0xffffffffu, idx, min(1, n - 1));
            int s2 = __shfl_sync(0xffffffffu, idx, min(2, n - 1));
            int s3 = __shfl_sync(0xffffffffu, idx, min(3, n - 1));
            a0 = ld_row(h, s0, lane); a1 = ld_row(h, s1, lane);
            a2 = ld_row(h, s2, lane); a3 = ld_row(h, s3, lane);
        }

        for (int t = 0; t < n; t += 4) {
            float4 c0 = a0, c1 = a1, c2 = a2, c3 = a3;

            if (t + 4 < n) {   // prefetch next group
                int u0 = __shfl_sync(0xffffffffu, idx, t + 4);
                int u1 = __shfl_sync(0xffffffffu, idx, min(t + 5, n - 1));
                int u2 = __shfl_sync(0xffffffffu, idx, min(t + 6, n - 1));
                int u3 = __shfl_sync(0xffffffffu, idx, min(t + 7, n - 1));
                a0 = ld_row(h, u0, lane); a1 = ld_row(h, u1, lane);
                a2 = ld_row(h, u2, lane); a3 = ld_row(h, u3, lane);
            }

            float d0 = c0.x*b.x + c0.y*b.y + c0.z*b.z + c0.w*b.w;
            float d1 = c1.x*b.x + c1.y*b.y + c1.z*b.z + c1.w*b.w;
            float d2 = c2.x*b.x + c2.y*b.y + c2.z*b.z + c2.w*b.w;
            float d3 = c3.x*b.x + c3.y*b.y + c3.z*b.z + c3.w*b.w;
#pragma unroll
            for (int o = 16; o; o >>= 1) {   // 4 independent chains interleaved
                d0 += __shfl_xor_sync(0xffffffffu, d0, o);
                d1 += __shfl_xor_sync(0xffffffffu, d1, o);
                d2 += __shfl_xor_sync(0xffffffffu, d2, o);
                d3 += __shfl_xor_sync(0xffffffffu, d3, o);
            }
            float al0 = __fdividef(1.0f, 1.0f + __expf(-d0));
            float al1 = (t + 1 < n) ? __fdividef(1.0f, 1.0f + __expf(-d1)) : 0.f;
            float al2 = (t + 2 < n) ? __fdividef(1.0f, 1.0f + __expf(-d2)) : 0.f;
            float al3 = (t + 3 < n) ? __fdividef(1.0f, 1.0f + __expf(-d3)) : 0.f;

            acc.x = fmaf(al0, c0.x, fmaf(al1, c1.x, fmaf(al2, c2.x, fmaf(al3, c3.x, acc.x))));
            acc.y = fmaf(al0, c0.y, fmaf(al1, c1.y, fmaf(al2, c2.y, fmaf(al3, c3.y, acc.y))));
            acc.z = fmaf(al0, c0.z, fmaf(al1, c1.z, fmaf(al2, c2.z, fmaf(al3, c3.z, acc.z))));
            acc.w = fmaf(al0, c0.w, fmaf(al1, c1.w, fmaf(al2, c2.w, fmaf(al3, c3.w, acc.w))));
        }
    }

    unsigned base = (unsigned)row * DIM + (unsigned)lane * 4;
    acc.x += SIGMA_F * jax_normal(k0, k1, base + 0);
    acc.y += SIGMA_F * jax_normal(k0, k1, base + 1);
    acc.z += SIGMA_F * jax_normal(k0, k1, base + 2);
    acc.w += SIGMA_F * jax_normal(k0, k1, base + 3);

    float ss = acc.x*acc.x + acc.y*acc.y + acc.z*acc.z + acc.w*acc.w;
#pragma unroll
    for (int o = 16; o; o >>= 1) ss += __shfl_xor_sync(0xffffffffu, ss, o);
    float inv = 1.0f / fmaxf(sqrtf(ss), 1e-12f);
    acc.x *= inv; acc.y *= inv; acc.z *= inv; acc.w *= inv;

    ((float4*)(out + (size_t)row * DIM))[lane] = acc;
}

// ---------------------------------------------------------------------------
// launch
// ---------------------------------------------------------------------------
extern "C" void kernel_launch(void* const* d_in, const int* in_sizes, int n_in,
                              void* d_out, int out_size)
{
    int i_x = 0, i_e = 1;
    if (in_sizes[0] != NNODES * DIM) { i_x = 1; i_e = 0; }
    const float* x  = (const float*)d_in[i_x];
    const void*  ei = d_in[i_e];
    int E = in_sizes[i_e] / 2;

    float* out = (float*)d_out;

    // fold-like split of jax.random.key(1) into NHOPS subkeys (exact)
    unsigned keys[NHOPS][2];
    for (unsigned k = 0; k < NHOPS; ++k)
        threefry2x32(0u, 1u, 0u, k, keys[k][0], keys[k][1]);

    const int ROW_BLOCKS  = (NNODES * 32 + 255) / 256;
    const int EDGE_BLOCKS = (E + 255) / 256;

    init_kernel<<<ROW_BLOCKS, 256>>>(x, out);
    hist_kernel<<<EDGE_BLOCKS, 256>>>(ei, E);
    scan1_kernel<<<NCHUNK, 256>>>();
    scan2_kernel<<<1, 256>>>();
    scan3_kernel<<<NCHUNK, 256>>>(E);
    scatter_kernel<<<EDGE_BLOCKS, 256>>>(ei, E);

    for (int k = 0; k < NHOPS; ++k) {
        hop_fused_kernel<<<ROW_BLOCKS, 256>>>(out + (size_t)k * NNODES * DIM,
                                              out + (size_t)(k + 1) * NNODES * DIM,
                                              keys[k][0], keys[k][1]);
    }
}